// round 3
// baseline (speedup 1.0000x reference)
#include <cuda_runtime.h>
#include <cstdint>

#define L_LEVELS 12
#define T_SIZE   (1u << 19)
#define T_MASK   (T_SIZE - 1u)
#define N_POINTS 524288
#define D_OUT    257
#define FEAT     24          // L * F
#define BLOCK    128         // threads per block = points per block (4 warps)
#define EMB_PAD  28          // padded row stride in floats (16B aligned, 7 float4s)

// ---------- packed f32x2 helpers (Blackwell FFMA2 path) ----------
__device__ __forceinline__ unsigned long long pack2(float lo, float hi) {
    unsigned long long r;
    asm("mov.b64 %0, {%1, %2};" : "=l"(r) : "f"(lo), "f"(hi));
    return r;
}
__device__ __forceinline__ void unpack2(unsigned long long v, float& lo, float& hi) {
    asm("mov.b64 {%0, %1}, %2;" : "=f"(lo), "=f"(hi) : "l"(v));
}
__device__ __forceinline__ unsigned long long fma2(unsigned long long a,
                                                   unsigned long long b,
                                                   unsigned long long c) {
    unsigned long long d;
    asm("fma.rn.f32x2 %0, %1, %2, %3;" : "=l"(d) : "l"(a), "l"(b), "l"(c));
    return d;
}

// Per-level grid resolutions: floor(16 * growth^l), growth = exp(ln(128)/11).
__device__ __constant__ float RESF[L_LEVELS] = {
    16.f, 24.f, 38.f, 60.f, 93.f, 145.f, 225.f, 350.f, 545.f, 847.f, 1317.f, 2048.f
};

__global__ __launch_bounds__(BLOCK, 6)
void hashgrid_fused_kernel(const float*  __restrict__ xin,    // [N,3]
                           const float2* __restrict__ tab,    // [12, T] of float2
                           const float*  __restrict__ W,      // [24, 257]
                           const float*  __restrict__ bias,   // [257]
                           float*        __restrict__ out)    // [N, 257]
{
    __shared__ float semb[BLOCK][EMB_PAD];  // 24 features/row, padded to 28
    __shared__ float wc256[FEAT];           // W[:,256]
    __shared__ float b256s;

    const int tid = threadIdx.x;

    if (tid < FEAT) wc256[tid] = W[tid * D_OUT + 256];
    if (tid == FEAT) b256s = bias[256];
    __syncthreads();

    // ---------------- Phase 1: hash encode (thread = point) ----------------
    const int p = blockIdx.x * BLOCK + tid;
    const float x = xin[3 * p + 0];
    const float y = xin[3 * p + 1];
    const float z = xin[3 * p + 2];

    const unsigned P1 = 2654435761u;
    const unsigned P2 = 805459861u;

    float acc256 = b256s;

#pragma unroll
    for (int l = 0; l < L_LEVELS; l++) {
        const float resf = RESF[l];
        const float2* tl = tab + (size_t)l * T_SIZE;

        float px = x * resf, py = y * resf, pz = z * resf;
        float fx = floorf(px), fy = floorf(py), fz = floorf(pz);
        float tx = px - fx,   ty = py - fy,   tz = pz - fz;

        unsigned cx = (unsigned)fx, cy = (unsigned)fy, cz = (unsigned)fz;
        unsigned hx0 = cx,        hx1 = cx + 1u;
        unsigned hy0 = cy * P1,   hy1 = hy0 + P1;
        unsigned hz0 = cz * P2,   hz1 = hz0 + P2;

        unsigned idx[8];
        idx[0] = (hx0 ^ hy0 ^ hz0) & T_MASK;
        idx[1] = (hx0 ^ hy0 ^ hz1) & T_MASK;
        idx[2] = (hx0 ^ hy1 ^ hz0) & T_MASK;
        idx[3] = (hx0 ^ hy1 ^ hz1) & T_MASK;
        idx[4] = (hx1 ^ hy0 ^ hz0) & T_MASK;
        idx[5] = (hx1 ^ hy0 ^ hz1) & T_MASK;
        idx[6] = (hx1 ^ hy1 ^ hz0) & T_MASK;
        idx[7] = (hx1 ^ hy1 ^ hz1) & T_MASK;

        float2 f[8];
#pragma unroll
        for (int i = 0; i < 8; i++) f[i] = __ldg(tl + idx[i]);

        const float ux = 1.0f - tx, uy = 1.0f - ty, uz = 1.0f - tz;
        float wxy[4];
        wxy[0] = ux * uy;
        wxy[1] = ux * ty;
        wxy[2] = tx * uy;
        wxy[3] = tx * ty;

        float e0 = 0.0f, e1 = 0.0f;
#pragma unroll
        for (int i = 0; i < 8; i++) {
            float w = wxy[i >> 1] * ((i & 1) ? tz : uz);
            e0 = fmaf(w, f[i].x, e0);
            e1 = fmaf(w, f[i].y, e1);
        }

        *reinterpret_cast<float2*>(&semb[tid][2 * l]) = make_float2(e0, e1);
        acc256 = fmaf(e0, wc256[2 * l + 0], acc256);
        acc256 = fmaf(e1, wc256[2 * l + 1], acc256);
    }

    // odd 257th column, streaming store
    __stcs(out + (size_t)p * D_OUT + 256, acc256);

    __syncthreads();

    // ------- Phase 2: GEMM head. Thread owns 2 strided columns {t, t+128}.
    // Packed over k: a = (e_{2k}, e_{2k+1}) * (W[2k][c], W[2k+1][c]); horizontal add at end.
    unsigned long long wreg[L_LEVELS][2];   // 12 k-pairs x 2 columns (48 regs)
#pragma unroll
    for (int kk = 0; kk < L_LEVELS; kk++) {
#pragma unroll
        for (int c = 0; c < 2; c++) {
            int col = tid + 128 * c;
            wreg[kk][c] = pack2(W[(2 * kk) * D_OUT + col], W[(2 * kk + 1) * D_OUT + col]);
        }
    }
    float breg[2];
#pragma unroll
    for (int c = 0; c < 2; c++) breg[c] = bias[tid + 128 * c];

    float* outb = out + (size_t)blockIdx.x * BLOCK * D_OUT;

    for (int r = 0; r < BLOCK; r += 2) {
        const float4* erow0 = reinterpret_cast<const float4*>(&semb[r][0]);
        const float4* erow1 = reinterpret_cast<const float4*>(&semb[r + 1][0]);
        unsigned long long a00 = 0, a01 = 0, a10 = 0, a11 = 0;
#pragma unroll
        for (int q = 0; q < 6; q++) {
            float4 e4a = erow0[q];               // broadcast LDS.128: 4 features, row r
            float4 e4b = erow1[q];               // row r+1
            unsigned long long p0a = pack2(e4a.x, e4a.y);
            unsigned long long p1a = pack2(e4a.z, e4a.w);
            unsigned long long p0b = pack2(e4b.x, e4b.y);
            unsigned long long p1b = pack2(e4b.z, e4b.w);
            a00 = fma2(p0a, wreg[2 * q][0], a00);  a00 = fma2(p1a, wreg[2 * q + 1][0], a00);
            a01 = fma2(p0a, wreg[2 * q][1], a01);  a01 = fma2(p1a, wreg[2 * q + 1][1], a01);
            a10 = fma2(p0b, wreg[2 * q][0], a10);  a10 = fma2(p1b, wreg[2 * q + 1][0], a10);
            a11 = fma2(p0b, wreg[2 * q][1], a11);  a11 = fma2(p1b, wreg[2 * q + 1][1], a11);
        }
        float lo, hi;
        float* orow0 = outb + (size_t)r * D_OUT;
        float* orow1 = orow0 + D_OUT;
        unpack2(a00, lo, hi); __stcs(orow0 + tid,       lo + hi + breg[0]);
        unpack2(a01, lo, hi); __stcs(orow0 + tid + 128, lo + hi + breg[1]);
        unpack2(a10, lo, hi); __stcs(orow1 + tid,       lo + hi + breg[0]);
        unpack2(a11, lo, hi); __stcs(orow1 + tid + 128, lo + hi + breg[1]);
    }
}

extern "C" void kernel_launch(void* const* d_in, const int* in_sizes, int n_in,
                              void* d_out, int out_size) {
    const float*  xin  = (const float*) d_in[0];   // [N,3]
    const float2* tab  = (const float2*)d_in[1];   // [12,T,2] -> float2
    const float*  W    = (const float*) d_in[2];   // [24,257]
    const float*  bias = (const float*) d_in[3];   // [257]
    float* out = (float*)d_out;

    dim3 grid(N_POINTS / BLOCK);   // 4096 blocks, 128 points each
    hashgrid_fused_kernel<<<grid, BLOCK>>>(xin, tab, W, bias, out);
}

// round 4
// speedup vs baseline: 1.0480x; 1.0480x over previous
#include <cuda_runtime.h>
#include <cstdint>

#define L_LEVELS 12
#define T_SIZE   (1u << 19)
#define T_MASK   (T_SIZE - 1u)
#define N_POINTS 524288
#define D_OUT    257
#define FEAT     24          // L * F
#define BLOCK    64          // threads per block = points per block (2 warps)
#define EMB_PAD  28          // padded row stride in floats (16B aligned, 7 float4s)

// ---------- packed f32x2 helpers (Blackwell FFMA2 path) ----------
__device__ __forceinline__ unsigned long long pack2(float lo, float hi) {
    unsigned long long r;
    asm("mov.b64 %0, {%1, %2};" : "=l"(r) : "f"(lo), "f"(hi));
    return r;
}
__device__ __forceinline__ void unpack2(unsigned long long v, float& lo, float& hi) {
    asm("mov.b64 {%0, %1}, %2;" : "=f"(lo), "=f"(hi) : "l"(v));
}
__device__ __forceinline__ unsigned long long fma2(unsigned long long a,
                                                   unsigned long long b,
                                                   unsigned long long c) {
    unsigned long long d;
    asm("fma.rn.f32x2 %0, %1, %2, %3;" : "=l"(d) : "l"(a), "l"(b), "l"(c));
    return d;
}

// Per-level grid resolutions: floor(16 * growth^l), growth = exp(ln(128)/11).
__device__ __constant__ float RESF[L_LEVELS] = {
    16.f, 24.f, 38.f, 60.f, 93.f, 145.f, 225.f, 350.f, 545.f, 847.f, 1317.f, 2048.f
};

// Compute the 8 corner hashes for one level and ISSUE the 8 gathers.
// Loads land in f[8]; consumption (and the scoreboard wait) happens later.
__device__ __forceinline__ void level_issue(float x, float y, float z, int l,
                                            const float2* __restrict__ tab,
                                            float2 f[8], float fr[3])
{
    const unsigned P1 = 2654435761u;
    const unsigned P2 = 805459861u;
    const float resf = RESF[l];
    const float2* tl = tab + (size_t)l * T_SIZE;

    float px = x * resf, py = y * resf, pz = z * resf;
    float fx = floorf(px), fy = floorf(py), fz = floorf(pz);
    fr[0] = px - fx; fr[1] = py - fy; fr[2] = pz - fz;

    unsigned cx = (unsigned)fx, cy = (unsigned)fy, cz = (unsigned)fz;
    unsigned hx0 = cx,        hx1 = cx + 1u;
    unsigned hy0 = cy * P1,   hy1 = hy0 + P1;
    unsigned hz0 = cz * P2,   hz1 = hz0 + P2;

    f[0] = __ldg(tl + ((hx0 ^ hy0 ^ hz0) & T_MASK));
    f[1] = __ldg(tl + ((hx0 ^ hy0 ^ hz1) & T_MASK));
    f[2] = __ldg(tl + ((hx0 ^ hy1 ^ hz0) & T_MASK));
    f[3] = __ldg(tl + ((hx0 ^ hy1 ^ hz1) & T_MASK));
    f[4] = __ldg(tl + ((hx1 ^ hy0 ^ hz0) & T_MASK));
    f[5] = __ldg(tl + ((hx1 ^ hy0 ^ hz1) & T_MASK));
    f[6] = __ldg(tl + ((hx1 ^ hy1 ^ hz0) & T_MASK));
    f[7] = __ldg(tl + ((hx1 ^ hy1 ^ hz1) & T_MASK));
}

// Trilinear blend of 8 gathered features -> (e0,e1)
__device__ __forceinline__ void level_consume(const float2 f[8], const float fr[3],
                                              float& e0, float& e1)
{
    const float tx = fr[0], ty = fr[1], tz = fr[2];
    const float ux = 1.0f - tx, uy = 1.0f - ty, uz = 1.0f - tz;
    float wxy[4];
    wxy[0] = ux * uy;
    wxy[1] = ux * ty;
    wxy[2] = tx * uy;
    wxy[3] = tx * ty;

    e0 = 0.0f; e1 = 0.0f;
#pragma unroll
    for (int i = 0; i < 8; i++) {
        float w = wxy[i >> 1] * ((i & 1) ? tz : uz);
        e0 = fmaf(w, f[i].x, e0);
        e1 = fmaf(w, f[i].y, e1);
    }
}

__global__ __launch_bounds__(BLOCK, 8)
void hashgrid_fused_kernel(const float*  __restrict__ xin,    // [N,3]
                           const float2* __restrict__ tab,    // [12, T] of float2
                           const float*  __restrict__ W,      // [24, 257]
                           const float*  __restrict__ bias,   // [257]
                           float*        __restrict__ out)    // [N, 257]
{
    __shared__ float semb[BLOCK][EMB_PAD];  // 24 features/row, padded to 28
    __shared__ float wc256[FEAT];           // W[:,256]
    __shared__ float b256s;

    const int tid = threadIdx.x;

    if (tid < FEAT) wc256[tid] = W[tid * D_OUT + 256];
    if (tid == FEAT) b256s = bias[256];
    __syncthreads();

    // ---------------- Phase 1: hash encode (thread = point) ----------------
    // 2-level software pipeline: level l+1's 8 gathers are in flight while
    // level l's trilinear blend executes (16 outstanding LDG.64 per thread).
    const int p = blockIdx.x * BLOCK + tid;
    const float x = xin[3 * p + 0];
    const float y = xin[3 * p + 1];
    const float z = xin[3 * p + 2];

    float acc256 = b256s;

    float2 fbuf[2][8];
    float  frb[2][3];

    level_issue(x, y, z, 0, tab, fbuf[0], frb[0]);

#pragma unroll
    for (int l = 0; l < L_LEVELS; l++) {
        const int cur = l & 1;
        if (l + 1 < L_LEVELS)
            level_issue(x, y, z, l + 1, tab, fbuf[(l + 1) & 1], frb[(l + 1) & 1]);

        float e0, e1;
        level_consume(fbuf[cur], frb[cur], e0, e1);

        *reinterpret_cast<float2*>(&semb[tid][2 * l]) = make_float2(e0, e1);
        acc256 = fmaf(e0, wc256[2 * l + 0], acc256);
        acc256 = fmaf(e1, wc256[2 * l + 1], acc256);
    }

    // odd 257th column, streaming store
    __stcs(out + (size_t)p * D_OUT + 256, acc256);

    // ------- Phase 2 weight prefetch (independent of semb; overlaps barrier) ----
    unsigned long long wreg[L_LEVELS][4];   // 12 k-pairs x 4 columns (96 regs)
#pragma unroll
    for (int kk = 0; kk < L_LEVELS; kk++) {
#pragma unroll
        for (int c = 0; c < 4; c++) {
            int col = tid + 64 * c;
            wreg[kk][c] = pack2(W[(2 * kk) * D_OUT + col], W[(2 * kk + 1) * D_OUT + col]);
        }
    }
    float breg[4];
#pragma unroll
    for (int c = 0; c < 4; c++) breg[c] = bias[tid + 64 * c];

    __syncthreads();

    // ------- Phase 2: GEMM head. Thread owns 4 strided columns {t, t+64, t+128, t+192}.
    float* outb = out + (size_t)blockIdx.x * BLOCK * D_OUT;

#pragma unroll 2
    for (int r = 0; r < BLOCK; r++) {
        const float4* erow = reinterpret_cast<const float4*>(&semb[r][0]);
        unsigned long long a0 = 0, a1 = 0, a2 = 0, a3 = 0;
#pragma unroll
        for (int q = 0; q < 6; q++) {
            float4 e4 = erow[q];                 // broadcast LDS.128: 4 features
            unsigned long long p0 = pack2(e4.x, e4.y);   // (e_{4q},   e_{4q+1})
            unsigned long long p1 = pack2(e4.z, e4.w);   // (e_{4q+2}, e_{4q+3})
            a0 = fma2(p0, wreg[2 * q][0], a0);  a0 = fma2(p1, wreg[2 * q + 1][0], a0);
            a1 = fma2(p0, wreg[2 * q][1], a1);  a1 = fma2(p1, wreg[2 * q + 1][1], a1);
            a2 = fma2(p0, wreg[2 * q][2], a2);  a2 = fma2(p1, wreg[2 * q + 1][2], a2);
            a3 = fma2(p0, wreg[2 * q][3], a3);  a3 = fma2(p1, wreg[2 * q + 1][3], a3);
        }
        float lo, hi;
        float* orow = outb + (size_t)r * D_OUT;
        unpack2(a0, lo, hi); __stcs(orow + tid,       lo + hi + breg[0]);
        unpack2(a1, lo, hi); __stcs(orow + tid +  64, lo + hi + breg[1]);
        unpack2(a2, lo, hi); __stcs(orow + tid + 128, lo + hi + breg[2]);
        unpack2(a3, lo, hi); __stcs(orow + tid + 192, lo + hi + breg[3]);
    }
}

extern "C" void kernel_launch(void* const* d_in, const int* in_sizes, int n_in,
                              void* d_out, int out_size) {
    const float*  xin  = (const float*) d_in[0];   // [N,3]
    const float2* tab  = (const float2*)d_in[1];   // [12,T,2] -> float2
    const float*  W    = (const float*) d_in[2];   // [24,257]
    const float*  bias = (const float*) d_in[3];   // [257]
    float* out = (float*)d_out;

    dim3 grid(N_POINTS / BLOCK);   // 8192 blocks, 64 points each
    hashgrid_fused_kernel<<<grid, BLOCK>>>(xin, tab, W, bias, out);
}